// round 1
// baseline (speedup 1.0000x reference)
#include <cuda_runtime.h>
#include <cuda_bf16.h>

#define DIN   128
#define DOUT  128
#define MAXN  100000
#define BN_EPS 1e-5f

// Scratch (allocation-free rule: __device__ globals)
__device__ float g_hop1[(size_t)MAXN * DIN];   // SpMM result [N,128]
__device__ int   g_rowptr[MAXN + 1];
// [0..255]=colsum, [256..511]=colsumsq, [512..767]=scale, [768..1023]=shift
__device__ float g_stats[1024];

// ---------------------------------------------------------------------------
__global__ void zero_stats_kernel() {
    int i = threadIdx.x;          // 512 threads
    g_stats[i] = 0.0f;
}

// adj_rows is sorted; scatter row boundaries into CSR row_ptr.
__global__ void build_rowptr_kernel(const int* __restrict__ rows, int E, int N) {
    int e = blockIdx.x * blockDim.x + threadIdx.x;
    if (e >= E) return;
    int r = rows[e];
    int prev = (e == 0) ? -1 : rows[e - 1];
    for (int rr = prev + 1; rr <= r; rr++) g_rowptr[rr] = e;
    if (e == E - 1) {
        for (int rr = r + 1; rr <= N; rr++) g_rowptr[rr] = E;
    }
}

// hop1[n,:] = sum_e val[e] * feat[col[e],:] over edges with row==n.
// One 128-thread block per node; thread d owns feature dim d. feat fits in L2.
__global__ void spmm_kernel(const float* __restrict__ feat,
                            const float* __restrict__ vals,
                            const int*   __restrict__ cols) {
    int n = blockIdx.x;
    int d = threadIdx.x;
    int s = g_rowptr[n];
    int e = g_rowptr[n + 1];
    float acc = 0.0f;
    for (int t = s; t < e; t++) {
        float v = __ldg(&vals[t]);
        int   c = __ldg(&cols[t]);
        acc = fmaf(v, __ldg(&feat[(size_t)c * DIN + d]), acc);
    }
    g_hop1[(size_t)n * DIN + d] = acc;
}

// ---------------------------------------------------------------------------
// Fused GEMM: out[:, col_off..col_off+127] = relu(X @ W) + bias
// 128x128 block tile, full K=128 streamed in BK=16 chunks, 256 threads,
// 8x8 register micro-tile per thread (split 4+4 in each dim for conflict-free
// float4 smem reads). Epilogue accumulates per-column sum/sumsq for BatchNorm.
#define BM 128
#define BK 16

__global__ __launch_bounds__(256, 2)
void gemm_relu_kernel(const float* __restrict__ X,
                      const float* __restrict__ W,
                      const float* __restrict__ bias,
                      float* __restrict__ out,
                      int N, int col_off) {
    __shared__ float As[BK][BM];    // As[k][m]  (transposed on load)
    __shared__ float Bs[BK][128];   // Bs[k][n]
    __shared__ float red_sum[128];
    __shared__ float red_sq[128];

    int tid = threadIdx.x;
    int tx = tid & 15;              // col group
    int ty = tid >> 4;              // row group
    int m0 = blockIdx.x * BM;

    if (tid < 128) { red_sum[tid] = 0.0f; red_sq[tid] = 0.0f; }

    float acc[8][8];
#pragma unroll
    for (int i = 0; i < 8; i++)
#pragma unroll
        for (int j = 0; j < 8; j++) acc[i][j] = 0.0f;

    for (int k0 = 0; k0 < DIN; k0 += BK) {
        // Load A tile (128 rows x 16 k) transposed into As[k][m]
        {
            int row = tid >> 2;             // 0..63
            int kq  = (tid & 3) * 4;        // 0,4,8,12
#pragma unroll
            for (int h = 0; h < 2; h++) {
                int m  = row + h * 64;
                int gr = m0 + m;
                float4 v = make_float4(0.f, 0.f, 0.f, 0.f);
                if (gr < N)
                    v = *(const float4*)&X[(size_t)gr * DIN + k0 + kq];
                As[kq + 0][m] = v.x;
                As[kq + 1][m] = v.y;
                As[kq + 2][m] = v.z;
                As[kq + 3][m] = v.w;
            }
        }
        // Load W tile (16 k x 128 n) straight into Bs[k][n]
        {
            int kr = tid >> 5;              // 0..7
            int c4 = (tid & 31) * 4;
#pragma unroll
            for (int h = 0; h < 2; h++) {
                int k = kr + h * 8;
                *(float4*)&Bs[k][c4] =
                    *(const float4*)&W[(size_t)(k0 + k) * DOUT + c4];
            }
        }
        __syncthreads();

#pragma unroll
        for (int kk = 0; kk < BK; kk++) {
            float a[8], b[8];
            *(float4*)&a[0] = *(const float4*)&As[kk][ty * 4];
            *(float4*)&a[4] = *(const float4*)&As[kk][64 + ty * 4];
            *(float4*)&b[0] = *(const float4*)&Bs[kk][tx * 4];
            *(float4*)&b[4] = *(const float4*)&Bs[kk][64 + tx * 4];
#pragma unroll
            for (int i = 0; i < 8; i++)
#pragma unroll
                for (int j = 0; j < 8; j++)
                    acc[i][j] = fmaf(a[i], b[j], acc[i][j]);
        }
        __syncthreads();
    }

    // Epilogue: relu + bias, write out, per-column partial sums
    float bz[8];
#pragma unroll
    for (int j = 0; j < 8; j++) {
        int c = (j < 4) ? tx * 4 + j : 64 + tx * 4 + (j - 4);
        bz[j] = __ldg(&bias[c]);
    }

    float psum[8], psq[8];
#pragma unroll
    for (int j = 0; j < 8; j++) { psum[j] = 0.0f; psq[j] = 0.0f; }

#pragma unroll
    for (int i = 0; i < 8; i++) {
        int m  = (i < 4) ? ty * 4 + i : 64 + ty * 4 + (i - 4);
        int gr = m0 + m;
        if (gr >= N) continue;
#pragma unroll
        for (int jh = 0; jh < 2; jh++) {
            float4 v;
            float r0 = fmaxf(acc[i][jh * 4 + 0], 0.f) + bz[jh * 4 + 0];
            float r1 = fmaxf(acc[i][jh * 4 + 1], 0.f) + bz[jh * 4 + 1];
            float r2 = fmaxf(acc[i][jh * 4 + 2], 0.f) + bz[jh * 4 + 2];
            float r3 = fmaxf(acc[i][jh * 4 + 3], 0.f) + bz[jh * 4 + 3];
            v.x = r0; v.y = r1; v.z = r2; v.w = r3;
            int c0 = (jh == 0) ? tx * 4 : 64 + tx * 4;
            *(float4*)&out[(size_t)gr * (2 * DOUT) + col_off + c0] = v;
            psum[jh * 4 + 0] += r0; psq[jh * 4 + 0] += r0 * r0;
            psum[jh * 4 + 1] += r1; psq[jh * 4 + 1] += r1 * r1;
            psum[jh * 4 + 2] += r2; psq[jh * 4 + 2] += r2 * r2;
            psum[jh * 4 + 3] += r3; psq[jh * 4 + 3] += r3 * r3;
        }
    }
#pragma unroll
    for (int j = 0; j < 8; j++) {
        int c = (j < 4) ? tx * 4 + j : 64 + tx * 4 + (j - 4);
        atomicAdd(&red_sum[c], psum[j]);
        atomicAdd(&red_sq[c],  psq[j]);
    }
    __syncthreads();
    if (tid < 128) {
        atomicAdd(&g_stats[col_off + tid],        red_sum[tid]);
        atomicAdd(&g_stats[256 + col_off + tid],  red_sq[tid]);
    }
}

// ---------------------------------------------------------------------------
__global__ void bn_finalize_kernel(const float* __restrict__ gamma,
                                   const float* __restrict__ beta,
                                   int N) {
    int c = threadIdx.x;                        // 256 threads
    float inv_n = 1.0f / (float)N;
    float mean = g_stats[c] * inv_n;
    float var  = g_stats[256 + c] * inv_n - mean * mean;
    float s = gamma[c] * rsqrtf(var + BN_EPS);
    g_stats[512 + c] = s;
    g_stats[768 + c] = beta[c] - mean * s;
}

__global__ void bn_apply_kernel(float* __restrict__ out, size_t total4) {
    size_t i = (size_t)blockIdx.x * blockDim.x + threadIdx.x;
    size_t stride = (size_t)gridDim.x * blockDim.x;
    const float4* scale4 = (const float4*)&g_stats[512];
    const float4* shift4 = (const float4*)&g_stats[768];
    for (; i < total4; i += stride) {
        int c4 = (int)(i & 63);                 // 64 float4 per 256-col row
        float4 s  = scale4[c4];
        float4 sh = shift4[c4];
        float4 v  = ((float4*)out)[i];
        v.x = fmaf(v.x, s.x, sh.x);
        v.y = fmaf(v.y, s.y, sh.y);
        v.z = fmaf(v.z, s.z, sh.z);
        v.w = fmaf(v.w, s.w, sh.w);
        ((float4*)out)[i] = v;
    }
}

// ---------------------------------------------------------------------------
extern "C" void kernel_launch(void* const* d_in, const int* in_sizes, int n_in,
                              void* d_out, int out_size) {
    const float* feat     = (const float*)d_in[0];
    const float* adj_vals = (const float*)d_in[1];
    const float* W0       = (const float*)d_in[2];
    const float* W1       = (const float*)d_in[3];
    const float* b0       = (const float*)d_in[4];
    const float* b1       = (const float*)d_in[5];
    const float* gamma    = (const float*)d_in[6];
    const float* beta     = (const float*)d_in[7];
    const int*   adj_rows = (const int*)d_in[8];
    const int*   adj_cols = (const int*)d_in[9];
    float* out = (float*)d_out;

    int N = in_sizes[0] / DIN;
    int E = in_sizes[1];

    float* hop1_ptr = nullptr;
    cudaGetSymbolAddress((void**)&hop1_ptr, g_hop1);

    zero_stats_kernel<<<1, 512>>>();
    build_rowptr_kernel<<<(E + 255) / 256, 256>>>(adj_rows, E, N);
    spmm_kernel<<<N, 128>>>(feat, adj_vals, adj_cols);

    int gblocks = (N + BM - 1) / BM;
    gemm_relu_kernel<<<gblocks, 256>>>(feat,     W0, b0, out, N, 0);
    gemm_relu_kernel<<<gblocks, 256>>>(hop1_ptr, W1, b1, out, N, DOUT);

    bn_finalize_kernel<<<1, 256>>>(gamma, beta, N);

    size_t total4 = (size_t)N * (2 * DOUT) / 4;
    int ablocks = (int)((total4 + 255) / 256);
    if (ablocks > 16384) ablocks = 16384;
    bn_apply_kernel<<<ablocks, 256>>>(out, total4);
}

// round 2
// speedup vs baseline: 1.2128x; 1.2128x over previous
#include <cuda_runtime.h>
#include <cuda_bf16.h>

#define DIN   128
#define DOUT  128
#define MAXN  100000
#define BN_EPS 1e-5f

// Scratch (allocation-free rule: __device__ globals)
__device__ float g_hop1[(size_t)MAXN * DIN];   // SpMM result [N,128]
__device__ int   g_rowptr[MAXN + 1];
// [0..255]=colsum, [256..511]=colsumsq, [512..767]=scale, [768..1023]=shift
__device__ float g_stats[1024];

// ---------------------------------------------------------------------------
__global__ void zero_stats_kernel() {
    int i = threadIdx.x;          // 512 threads
    g_stats[i] = 0.0f;
}

// adj_rows is sorted; scatter row boundaries into CSR row_ptr.
__global__ void build_rowptr_kernel(const int* __restrict__ rows, int E, int N) {
    int e = blockIdx.x * blockDim.x + threadIdx.x;
    if (e >= E) return;
    int r = rows[e];
    int prev = (e == 0) ? -1 : rows[e - 1];
    for (int rr = prev + 1; rr <= r; rr++) g_rowptr[rr] = e;
    if (e == E - 1) {
        for (int rr = r + 1; rr <= N; rr++) g_rowptr[rr] = E;
    }
}

// hop1[n,:] = sum_e val[e] * feat[col[e],:].  One warp per node, each lane
// owns a float4 (4 dims). 2-edge unroll for MLP. feat is L2-resident.
__global__ void spmm_kernel(const float* __restrict__ feat,
                            const float* __restrict__ vals,
                            const int*   __restrict__ cols,
                            int N) {
    int warp = (blockIdx.x * blockDim.x + threadIdx.x) >> 5;
    int lane = threadIdx.x & 31;
    if (warp >= N) return;
    int s = g_rowptr[warp];
    int e = g_rowptr[warp + 1];
    float4 acc0 = make_float4(0.f, 0.f, 0.f, 0.f);
    float4 acc1 = make_float4(0.f, 0.f, 0.f, 0.f);
    int t = s;
    for (; t + 1 < e; t += 2) {
        float v0 = __ldg(&vals[t]);
        float v1 = __ldg(&vals[t + 1]);
        int   c0 = __ldg(&cols[t]);
        int   c1 = __ldg(&cols[t + 1]);
        float4 x0 = __ldg(&((const float4*)&feat[(size_t)c0 * DIN])[lane]);
        float4 x1 = __ldg(&((const float4*)&feat[(size_t)c1 * DIN])[lane]);
        acc0.x = fmaf(v0, x0.x, acc0.x); acc0.y = fmaf(v0, x0.y, acc0.y);
        acc0.z = fmaf(v0, x0.z, acc0.z); acc0.w = fmaf(v0, x0.w, acc0.w);
        acc1.x = fmaf(v1, x1.x, acc1.x); acc1.y = fmaf(v1, x1.y, acc1.y);
        acc1.z = fmaf(v1, x1.z, acc1.z); acc1.w = fmaf(v1, x1.w, acc1.w);
    }
    if (t < e) {
        float v0 = __ldg(&vals[t]);
        int   c0 = __ldg(&cols[t]);
        float4 x0 = __ldg(&((const float4*)&feat[(size_t)c0 * DIN])[lane]);
        acc0.x = fmaf(v0, x0.x, acc0.x); acc0.y = fmaf(v0, x0.y, acc0.y);
        acc0.z = fmaf(v0, x0.z, acc0.z); acc0.w = fmaf(v0, x0.w, acc0.w);
    }
    acc0.x += acc1.x; acc0.y += acc1.y; acc0.z += acc1.z; acc0.w += acc1.w;
    ((float4*)&g_hop1[(size_t)warp * DIN])[lane] = acc0;
}

// ---------------------------------------------------------------------------
// Packed f32x2 helpers — ptxas never emits FFMA2 from C++; PTX-only path.
__device__ __forceinline__ void ffma2(unsigned long long& d,
                                      unsigned long long a,
                                      unsigned long long b) {
    asm("fma.rn.f32x2 %0, %1, %2, %3;" : "=l"(d) : "l"(a), "l"(b), "l"(d));
}
__device__ __forceinline__ unsigned long long pack2(float x) {
    unsigned long long r;
    unsigned int u = __float_as_uint(x);
    asm("mov.b64 %0, {%1, %1};" : "=l"(r) : "r"(u));
    return r;
}

// Fused GEMM: out[:, col_off..col_off+127] = relu(X @ W) + bias
// 128x128 block tile, BK=16 chunks, 256 threads, 8x8 micro-tile per thread.
// Accumulators packed as f32x2 pairs along the ROW dim so the A operand pairs
// come directly from the float4 SMEM load; only B needs per-k broadcast packs.
#define BM 128
#define BK 16

__global__ __launch_bounds__(256, 2)
void gemm_relu_kernel(const float* __restrict__ X,
                      const float* __restrict__ W,
                      const float* __restrict__ bias,
                      float* __restrict__ out,
                      int N, int col_off) {
    __shared__ float As[BK][BM];    // As[k][m]  (transposed on load)
    __shared__ float Bs[BK][128];   // Bs[k][n]
    __shared__ float red_sum[128];
    __shared__ float red_sq[128];

    int tid = threadIdx.x;
    int tx = tid & 15;              // col group
    int ty = tid >> 4;              // row group
    int m0 = blockIdx.x * BM;

    if (tid < 128) { red_sum[tid] = 0.0f; red_sq[tid] = 0.0f; }

    // acc2[ip][j]: ip=row-pair (i=2*ip, 2*ip+1), j=column 0..7
    unsigned long long acc2[4][8];
#pragma unroll
    for (int ip = 0; ip < 4; ip++)
#pragma unroll
        for (int j = 0; j < 8; j++) acc2[ip][j] = 0ull;

    for (int k0 = 0; k0 < DIN; k0 += BK) {
        // Load A tile (128 rows x 16 k) transposed into As[k][m]
        {
            int row = tid >> 2;             // 0..63
            int kq  = (tid & 3) * 4;        // 0,4,8,12
#pragma unroll
            for (int h = 0; h < 2; h++) {
                int m  = row + h * 64;
                int gr = m0 + m;
                float4 v = make_float4(0.f, 0.f, 0.f, 0.f);
                if (gr < N)
                    v = *(const float4*)&X[(size_t)gr * DIN + k0 + kq];
                As[kq + 0][m] = v.x;
                As[kq + 1][m] = v.y;
                As[kq + 2][m] = v.z;
                As[kq + 3][m] = v.w;
            }
        }
        // Load W tile (16 k x 128 n) straight into Bs[k][n]
        {
            int kr = tid >> 5;              // 0..7
            int c4 = (tid & 31) * 4;
#pragma unroll
            for (int h = 0; h < 2; h++) {
                int k = kr + h * 8;
                *(float4*)&Bs[k][c4] =
                    *(const float4*)&W[(size_t)(k0 + k) * DOUT + c4];
            }
        }
        __syncthreads();

#pragma unroll
        for (int kk = 0; kk < BK; kk++) {
            // A pairs straight from the 128-bit SMEM loads
            ulonglong2 alo = *(const ulonglong2*)&As[kk][ty * 4];
            ulonglong2 ahi = *(const ulonglong2*)&As[kk][64 + ty * 4];
            unsigned long long aa[4] = { alo.x, alo.y, ahi.x, ahi.y };
            float4 bl = *(const float4*)&Bs[kk][tx * 4];
            float4 bh = *(const float4*)&Bs[kk][64 + tx * 4];
            unsigned long long b2[8] = {
                pack2(bl.x), pack2(bl.y), pack2(bl.z), pack2(bl.w),
                pack2(bh.x), pack2(bh.y), pack2(bh.z), pack2(bh.w)
            };
#pragma unroll
            for (int ip = 0; ip < 4; ip++)
#pragma unroll
                for (int j = 0; j < 8; j++)
                    ffma2(acc2[ip][j], aa[ip], b2[j]);
        }
        __syncthreads();
    }

    // Epilogue: relu + bias, write out, per-column partial sums
    float bz[8];
#pragma unroll
    for (int j = 0; j < 8; j++) {
        int c = (j < 4) ? tx * 4 + j : 64 + tx * 4 + (j - 4);
        bz[j] = __ldg(&bias[c]);
    }

    float psum[8], psq[8];
#pragma unroll
    for (int j = 0; j < 8; j++) { psum[j] = 0.0f; psq[j] = 0.0f; }

#pragma unroll
    for (int i = 0; i < 8; i++) {
        int ip   = i >> 1;
        int half = i & 1;
        int m  = (i < 4) ? ty * 4 + i : 64 + ty * 4 + (i - 4);
        int gr = m0 + m;
        if (gr >= N) continue;
        // unpack this row's 8 accumulators
        float av[8];
#pragma unroll
        for (int j = 0; j < 8; j++) {
            unsigned int lo = (unsigned int)(acc2[ip][j] & 0xFFFFFFFFull);
            unsigned int hi = (unsigned int)(acc2[ip][j] >> 32);
            av[j] = __uint_as_float(half ? hi : lo);
        }
#pragma unroll
        for (int jh = 0; jh < 2; jh++) {
            float r0 = fmaxf(av[jh * 4 + 0], 0.f) + bz[jh * 4 + 0];
            float r1 = fmaxf(av[jh * 4 + 1], 0.f) + bz[jh * 4 + 1];
            float r2 = fmaxf(av[jh * 4 + 2], 0.f) + bz[jh * 4 + 2];
            float r3 = fmaxf(av[jh * 4 + 3], 0.f) + bz[jh * 4 + 3];
            float4 v = make_float4(r0, r1, r2, r3);
            int c0 = (jh == 0) ? tx * 4 : 64 + tx * 4;
            *(float4*)&out[(size_t)gr * (2 * DOUT) + col_off + c0] = v;
            psum[jh * 4 + 0] += r0; psq[jh * 4 + 0] += r0 * r0;
            psum[jh * 4 + 1] += r1; psq[jh * 4 + 1] += r1 * r1;
            psum[jh * 4 + 2] += r2; psq[jh * 4 + 2] += r2 * r2;
            psum[jh * 4 + 3] += r3; psq[jh * 4 + 3] += r3 * r3;
        }
    }
#pragma unroll
    for (int j = 0; j < 8; j++) {
        int c = (j < 4) ? tx * 4 + j : 64 + tx * 4 + (j - 4);
        atomicAdd(&red_sum[c], psum[j]);
        atomicAdd(&red_sq[c],  psq[j]);
    }
    __syncthreads();
    if (tid < 128) {
        atomicAdd(&g_stats[col_off + tid],        red_sum[tid]);
        atomicAdd(&g_stats[256 + col_off + tid],  red_sq[tid]);
    }
}

// ---------------------------------------------------------------------------
__global__ void bn_finalize_kernel(const float* __restrict__ gamma,
                                   const float* __restrict__ beta,
                                   int N) {
    int c = threadIdx.x;                        // 256 threads
    float inv_n = 1.0f / (float)N;
    float mean = g_stats[c] * inv_n;
    float var  = g_stats[256 + c] * inv_n - mean * mean;
    float s = gamma[c] * rsqrtf(var + BN_EPS);
    g_stats[512 + c] = s;
    g_stats[768 + c] = beta[c] - mean * s;
}

__global__ void bn_apply_kernel(float* __restrict__ out, size_t total4) {
    size_t i = (size_t)blockIdx.x * blockDim.x + threadIdx.x;
    size_t stride = (size_t)gridDim.x * blockDim.x;
    const float4* scale4 = (const float4*)&g_stats[512];
    const float4* shift4 = (const float4*)&g_stats[768];
    for (; i < total4; i += stride) {
        int c4 = (int)(i & 63);                 // 64 float4 per 256-col row
        float4 s  = scale4[c4];
        float4 sh = shift4[c4];
        float4 v  = ((float4*)out)[i];
        v.x = fmaf(v.x, s.x, sh.x);
        v.y = fmaf(v.y, s.y, sh.y);
        v.z = fmaf(v.z, s.z, sh.z);
        v.w = fmaf(v.w, s.w, sh.w);
        ((float4*)out)[i] = v;
    }
}

// ---------------------------------------------------------------------------
extern "C" void kernel_launch(void* const* d_in, const int* in_sizes, int n_in,
                              void* d_out, int out_size) {
    const float* feat     = (const float*)d_in[0];
    const float* adj_vals = (const float*)d_in[1];
    const float* W0       = (const float*)d_in[2];
    const float* W1       = (const float*)d_in[3];
    const float* b0       = (const float*)d_in[4];
    const float* b1       = (const float*)d_in[5];
    const float* gamma    = (const float*)d_in[6];
    const float* beta     = (const float*)d_in[7];
    const int*   adj_rows = (const int*)d_in[8];
    const int*   adj_cols = (const int*)d_in[9];
    float* out = (float*)d_out;

    int N = in_sizes[0] / DIN;
    int E = in_sizes[1];

    float* hop1_ptr = nullptr;
    cudaGetSymbolAddress((void**)&hop1_ptr, g_hop1);

    zero_stats_kernel<<<1, 512>>>();
    build_rowptr_kernel<<<(E + 255) / 256, 256>>>(adj_rows, E, N);
    int sblocks = (N * 32 + 255) / 256;
    spmm_kernel<<<sblocks, 256>>>(feat, adj_vals, adj_cols, N);

    int gblocks = (N + BM - 1) / BM;
    gemm_relu_kernel<<<gblocks, 256>>>(feat,     W0, b0, out, N, 0);
    gemm_relu_kernel<<<gblocks, 256>>>(hop1_ptr, W1, b1, out, N, DOUT);

    bn_finalize_kernel<<<1, 256>>>(gamma, beta, N);

    size_t total4 = (size_t)N * (2 * DOUT) / 4;
    int ablocks = (int)((total4 + 255) / 256);
    if (ablocks > 16384) ablocks = 16384;
    bn_apply_kernel<<<ablocks, 256>>>(out, total4);
}